// round 17
// baseline (speedup 1.0000x reference)
#include <cuda_runtime.h>
#include <cuda_fp16.h>

#define TN 1024
#define RMAXF 8.0f
#define RCUT2 36.0f
#define MAXAB 32768
#define MAXE  640000
#define MAXP  262144

// Radial table (fp16 lerp pairs): g16[i*48+o] = (g[i][o], g[i+1][o]),
// g[i][t*16+m] = (silu(rb(r_i)@w1[t]) @ w2[t])[m] / sqrt(20).
// g(r)==~0 for r > 5.8, so dropping r>6 edges is numerically free.
__device__ __align__(16) __half2 g16[TN * 48];
__device__ float act_tab[TN * 300];
__device__ float4 rw4[MAXAB];           // (dot(rep[t][a],w_out))_{t=0..2}, pad
__device__ __half rep16[3 * MAXAB * 128];
// per-probe linked list of contributing edges
__device__ float4 rec[MAXE];            // (c0,c1,c2, src-as-float)
__device__ int    nxt[MAXE];
__device__ int    head[MAXP];

// ---------------- 1: setup1 — act_tab + rep16/rw + head init (all flat) -----
__global__ void __launch_bounds__(256) setup1_kernel(
    const float* __restrict__ w1,
    const float* __restrict__ atom_rep, const float* __restrict__ w_out,
    int P, int AB, int actBlocks, int prepBlocks)
{
    int bid = blockIdx.x;
    int tid = threadIdx.x;

    if (bid < actBlocks) {
        // ids [bid*256, bid*256+255] span at most 2 distinct table indices i
        __shared__ float s_rb[2][10];
        int id0 = bid * 256;
        int i_lo = id0 / 300;
        if (tid < 20) {
            int which = tid / 10, k = tid % 10;
            int ii = min(i_lo + which, TN - 1);
            float r = (float)ii * (RMAXF / (float)(TN - 1));
            const float step = 4.0f / 9.0f;
            float d = (r - (float)k * step) / step;
            s_rb[which][k] = expf(-d * d) * 1.12f;
        }
        __syncthreads();
        int id = id0 + tid;
        if (id >= TN * 300) return;
        int i = id / 300, rem = id % 300;
        int t = rem / 100, j = rem % 100;
        const float* RB = s_rb[i - i_lo];
        const float* W1 = w1 + t * 1000 + j;
        float a = 0.f;
#pragma unroll
        for (int k = 0; k < 10; k++)
            a = fmaf(RB[k], __ldg(W1 + k * 100), a);
        act_tab[id] = a / (1.f + expf(-a));
    } else if (bid < actBlocks + prepBlocks) {
        // rep16 convert + rw dot: warp per row (row = t*AB + a)
        int row = (bid - actBlocks) * 8 + (tid >> 5);
        int lane = tid & 31;
        if (row >= 3 * AB) return;
        float4 a = __ldg((const float4*)atom_rep + (size_t)row * 32 + lane);
        __half2 h0 = __floats2half2_rn(a.x, a.y);
        __half2 h1 = __floats2half2_rn(a.z, a.w);
        uint2 u;
        u.x = *(unsigned*)&h0;
        u.y = *(unsigned*)&h1;
        ((uint2*)rep16)[(size_t)row * 32 + lane] = u;
        float4 wv = __ldg((const float4*)w_out + lane);
        float s = fmaf(a.x, wv.x, fmaf(a.y, wv.y, fmaf(a.z, wv.z, a.w * wv.w)));
#pragma unroll
        for (int off = 16; off > 0; off >>= 1)
            s += __shfl_xor_sync(0xFFFFFFFFu, s, off);
        if (lane == 0) {
            int t = row / AB, aa = row % AB;
            ((float*)rw4)[aa * 4 + t] = s;
        }
    } else {
        int idx = (bid - actBlocks - prepBlocks) * 256 + tid;
        if (idx < P) head[idx] = -1;
    }
}

// ---------------- 2: setup2 — output table, fp16 lerp pairs -----------------
__global__ void __launch_bounds__(256) setup2_kernel(const float* __restrict__ w2)
{
    int id = blockIdx.x * blockDim.x + threadIdx.x;
    if (id >= TN * 48) return;
    int i = id / 48, o = id % 48;
    int t = o >> 4, m = o & 15;
    const float* A0 = act_tab + i * 300 + t * 100;
    const float* A1 = act_tab + min(i + 1, TN - 1) * 300 + t * 100;
    const float* W = w2 + t * 1600 + m;
    float h0 = 0.f, h1 = 0.f;
#pragma unroll 4
    for (int j = 0; j < 100; j++) {
        float wv = __ldg(W + j * 16);
        h0 = fmaf(__ldg(A0 + j), wv, h0);
        h1 = fmaf(__ldg(A1 + j), wv, h1);
    }
    const float scale = 0.22360679774997896f;  // 1/sqrt(20)
    g16[id] = __floats2half2_rn(h0 * scale, h1 * scale);
}

// ---------------- 3: phase A — thread per edge, early r^2 exit --------------
__global__ void __launch_bounds__(256) phaseA_kernel(
    const float* __restrict__ atom_xyz,
    const float* __restrict__ probe_xyz,
    const int*   __restrict__ edges,
    const float* __restrict__ ped,
    const float* __restrict__ cell,
    int E, int n_edges_b, int n_atoms, int n_probes)
{
    int e = blockIdx.x * 256 + threadIdx.x;
    if (e >= E) return;

    int b = e / n_edges_b;
    int2 se = ((const int2*)edges)[e];
    int src_g = b * n_atoms + se.x;
    int dst_g = b * n_probes + se.y;
    float px = ped[3 * e], py = ped[3 * e + 1], pz = ped[3 * e + 2];
    const float* C = cell + b * 9;
    float dx = fmaf(px, __ldg(C + 0), fmaf(py, __ldg(C + 3), pz * __ldg(C + 6)));
    float dy = fmaf(px, __ldg(C + 1), fmaf(py, __ldg(C + 4), pz * __ldg(C + 7)));
    float dz = fmaf(px, __ldg(C + 2), fmaf(py, __ldg(C + 5), pz * __ldg(C + 8)));
    float vx = probe_xyz[3 * dst_g + 0] - atom_xyz[3 * src_g + 0] - dx;
    float vy = probe_xyz[3 * dst_g + 1] - atom_xyz[3 * src_g + 1] - dy;
    float vz = probe_xyz[3 * dst_g + 2] - atom_xyz[3 * src_g + 2] - dz;
    float r2 = fmaf(vx, vx, fmaf(vy, vy, vz * vz));
    if (r2 >= RCUT2) return;         // ~85% exit: no sqrt, no SH, no insert
                                     // survivors: r<6 -> i0 <= 767 < TN-1
    float r = sqrtf(r2);
    float f = r * ((float)(TN - 1) / RMAXF);
    int i0 = (int)f;
    float w = f - (float)i0;
    float rinv = 1.0f / fmaxf(r, 1e-9f);
    float x = vx * rinv, y = vy * rinv, z = vz * rinv;
    float x2 = x * x, y2 = y * y, z2 = z * z;

    const float s3  = 1.7320508075688772f;
    const float s15 = 3.872983346207417f;
    float sh[16];
    sh[0]  = 1.f;
    sh[1]  = s3 * x;
    sh[2]  = s3 * y;
    sh[3]  = s3 * z;
    sh[4]  = s15 * x * y;
    sh[5]  = s15 * y * z;
    sh[6]  = 1.118033988749895f * (3.f * z2 - 1.f);
    sh[7]  = s15 * x * z;
    sh[8]  = 1.9364916731037085f * (x2 - y2);
    sh[9]  = 2.091650066335189f * y * (3.f * x2 - y2);
    sh[10] = 10.246950765959598f * x * y * z;
    sh[11] = 1.6201851746019651f * y * (5.f * z2 - 1.f);
    sh[12] = 1.3228756555322954f * (5.f * z2 * z - 3.f * z);
    sh[13] = 1.6201851746019651f * x * (5.f * z2 - 1.f);
    sh[14] = 5.123475382979799f * z * (x2 - y2);
    sh[15] = 2.091650066335189f * x * (x2 - 3.f * y2);

    // table read: 12 aligned 16B loads (192 B contiguous per entry)
    const uint4* G = (const uint4*)(g16 + (size_t)i0 * 48);
    float sc[3];
#pragma unroll
    for (int t = 0; t < 3; t++) {
        float acc = 0.f;
#pragma unroll
        for (int q = 0; q < 4; q++) {
            uint4 u = __ldg(G + t * 4 + q);
            float2 p0 = __half22float2(*(__half2*)&u.x);
            float2 p1 = __half22float2(*(__half2*)&u.y);
            float2 p2 = __half22float2(*(__half2*)&u.z);
            float2 p3 = __half22float2(*(__half2*)&u.w);
            int mb = q * 4;
            acc = fmaf(sh[mb + 0], fmaf(w, p0.y - p0.x, p0.x), acc);
            acc = fmaf(sh[mb + 1], fmaf(w, p1.y - p1.x, p1.x), acc);
            acc = fmaf(sh[mb + 2], fmaf(w, p2.y - p2.x, p2.x), acc);
            acc = fmaf(sh[mb + 3], fmaf(w, p3.y - p3.x, p3.x), acc);
        }
        sc[t] = acc;
    }

    rec[e] = make_float4(sc[0], sc[1], sc[2], __int_as_float(src_g));
    nxt[e] = atomicExch(&head[dst_g], e);
}

// ---------------- 4: phase B — warp handles 4 probes -------------------------
__global__ void __launch_bounds__(128, 10) phaseB_kernel(
    float* __restrict__ probes, float* __restrict__ out, int P, int AB)
{
    int g = blockIdx.x * blockDim.x + threadIdx.x;
    int wrp = g >> 5;
    int lane = g & 31;
    int p0 = wrp * 4;
    if (p0 >= P) return;

    bool full4 = (p0 + 3 < P);
    int e[4];
    if (full4) {
        int4 h4 = __ldg((const int4*)(head + p0));   // one LDG.128
        e[0] = h4.x; e[1] = h4.y; e[2] = h4.z; e[3] = h4.w;
    } else {
#pragma unroll
        for (int k = 0; k < 4; k++)
            e[k] = (p0 + k < P) ? __ldg(&head[p0 + k]) : -1;
    }

    // fast path: all 4 probes empty (~22% of warps)
    if (full4 && (e[0] & e[1] & e[2] & e[3]) == -1) {
        float4 z = make_float4(0.f, 0.f, 0.f, 0.f);
#pragma unroll
        for (int k = 0; k < 4; k++)
            __stcs(&((float4*)(probes + (size_t)(p0 + k) * 128))[lane], z);
        if (lane == 0) __stcs((float4*)(out + p0), z);
        return;
    }

    size_t repT2 = (size_t)AB * 64;
    const __half2* rep2 = (const __half2*)rep16;

    float4 acc[4];
    float ov[4];
#pragma unroll
    for (int k = 0; k < 4; k++) {
        acc[k] = make_float4(0.f, 0.f, 0.f, 0.f);
        ov[k] = 0.f;
    }

    while (e[0] >= 0 || e[1] >= 0 || e[2] >= 0 || e[3] >= 0) {
        float4 c[4];
#pragma unroll
        for (int k = 0; k < 4; k++)
            if (e[k] >= 0) c[k] = __ldg(&rec[e[k]]);   // independent
#pragma unroll
        for (int k = 0; k < 4; k++) {
            if (e[k] < 0) continue;
            int src = __float_as_int(c[k].w);
            const __half2* pp = rep2 + (size_t)src * 64 + lane * 2;
            uint2 u0 = __ldg((const uint2*)pp);
            uint2 u1 = __ldg((const uint2*)(pp + repT2));
            uint2 u2 = __ldg((const uint2*)(pp + 2 * repT2));
            float2 a0 = __half22float2(*(__half2*)&u0.x);
            float2 b0 = __half22float2(*(__half2*)&u0.y);
            float2 a1 = __half22float2(*(__half2*)&u1.x);
            float2 b1 = __half22float2(*(__half2*)&u1.y);
            float2 a2 = __half22float2(*(__half2*)&u2.x);
            float2 b2 = __half22float2(*(__half2*)&u2.y);
            acc[k].x += fmaf(c[k].x, a0.x, fmaf(c[k].y, a1.x, c[k].z * a2.x));
            acc[k].y += fmaf(c[k].x, a0.y, fmaf(c[k].y, a1.y, c[k].z * a2.y));
            acc[k].z += fmaf(c[k].x, b0.x, fmaf(c[k].y, b1.x, c[k].z * b2.x));
            acc[k].w += fmaf(c[k].x, b0.y, fmaf(c[k].y, b1.y, c[k].z * b2.y));
            if (lane == 0) {
                float4 rwv = __ldg(&rw4[src]);       // one load, was three
                ov[k] += fmaf(c[k].x, rwv.x,
                         fmaf(c[k].y, rwv.y, c[k].z * rwv.z));
            }
            e[k] = __ldg(&nxt[e[k]]);
        }
    }

#pragma unroll
    for (int k = 0; k < 4; k++) {
        int p = p0 + k;
        if (p < P)
            __stcs(&((float4*)(probes + (size_t)p * 128))[lane], acc[k]);
    }
    if (lane == 0) {
        if (full4) {
            __stcs((float4*)(out + p0),
                   make_float4(ov[0], ov[1], ov[2], ov[3]));
        } else {
#pragma unroll
            for (int k = 0; k < 4; k++)
                if (p0 + k < P) out[p0 + k] = ov[k];
        }
    }
}

extern "C" void kernel_launch(void* const* d_in, const int* in_sizes, int n_in,
                              void* d_out, int out_size)
{
    const float* atom_xyz  = (const float*)d_in[0];
    const float* probe_xyz = (const float*)d_in[1];
    const int*   edges     = (const int*)d_in[2];
    const float* ped       = (const float*)d_in[3];
    const float* cell      = (const float*)d_in[4];
    const float* atom_rep  = (const float*)d_in[8];
    const float* w1        = (const float*)d_in[9];
    const float* w2        = (const float*)d_in[10];
    const float* w_out     = (const float*)d_in[11];

    int B         = in_sizes[4] / 9;
    int n_atoms   = in_sizes[0] / (3 * B);
    int n_probes  = in_sizes[1] / (3 * B);
    int n_edges_b = in_sizes[2] / (2 * B);
    int E  = B * n_edges_b;
    int AB = B * n_atoms;
    int P  = B * n_probes;

    float* out    = (float*)d_out;      // first P: (B,P) potential
    float* probes = out + P;            // next P*128: probe features

    int actBlocks  = (TN * 300 + 255) / 256;
    int prepBlocks = (3 * AB + 7) / 8;
    int headBlocks = (P + 255) / 256;
    setup1_kernel<<<actBlocks + prepBlocks + headBlocks, 256>>>(
        w1, atom_rep, w_out, P, AB, actBlocks, prepBlocks);
    setup2_kernel<<<(TN * 48 + 255) / 256, 256>>>(w2);
    phaseA_kernel<<<(E + 255) / 256, 256>>>(atom_xyz, probe_xyz, edges, ped,
                                            cell, E, n_edges_b, n_atoms,
                                            n_probes);
    int nwarp = (P + 3) / 4;
    phaseB_kernel<<<(nwarp * 32 + 127) / 128, 128>>>(probes, out, P, AB);
}